// round 12
// baseline (speedup 1.0000x reference)
#include <cuda_runtime.h>
#include <cstdint>

// RegL1Loss: out[b] = sum_{p,d} valid * |preds[b, idx] - val| / num_people[b]
// B=32, P=64, D=34, L=1048576. gts packed as [...,3] = (val, idx_as_float, flag).
//
// 4 CTAs per batch (grid=128) to spread the random-gather L1tex wavefront load
// across 4x more SMs (544 lines/SM instead of 2176). Cheapest-possible combine:
// each CTA plain-stores (partial_sum, partial_cnt) into a per-batch scratch
// slot, release-fence, one ticket atomic; last arriver acquire-fences, reads
// both float4/int4 slots with ld.global.cg (one LDG each), sums in fixed order
// (bitwise deterministic), divides, writes out[b], resets only the ticket.

#define B 32
#define P 64
#define D 34
#define PD (P * D)          // 2176
#define L 1048576
#define SPLITS 4
#define EPC (PD / SPLITS)   // 544 elements per CTA = 16 persons
#define PPC (EPC / D)       // 16
#define LOADERS (EPC / 4)   // 136 loader threads, 4 elements each
#define TPC 160             // 5 warps
#define NW (TPC / 32)

__device__ float4   g_part[B];    // partial sums, one lane per split
__device__ int4     g_pcnt[B];    // partial person counts
__device__ unsigned g_ticket[B];  // zero-init; winner resets each run

__global__ __launch_bounds__(TPC) void regl1_kernel(
    const float* __restrict__ preds,
    const float* __restrict__ gts,
    float* __restrict__ out)
{
    const int cta   = blockIdx.x;
    const int b     = cta >> 2;
    const int split = cta & 3;
    const int tid   = threadIdx.x;

    __shared__ int   pv[PPC];
    __shared__ float wsum[NW];

    if (tid < PPC) pv[tid] = 0;
    __syncthreads();

    float acc = 0.0f;
    if (tid < LOADERS) {
        // 12 consecutive floats per thread = 3 float4 loads (48B/thread).
        const float4* __restrict__ g4 =
            (const float4*)(gts + ((size_t)b * PD + split * EPC) * 3) +
            (size_t)tid * 3;
        const float* __restrict__ pr = preds + (size_t)b * L;

        float4 a0 = g4[0];
        float4 a1 = g4[1];
        float4 a2 = g4[2];

        float vals[4] = { a0.x, a0.w, a1.z, a2.y };
        float fidx[4] = { a0.y, a1.x, a1.w, a2.z };
        float flag[4] = { a0.z, a1.y, a2.x, a2.w };

        bool  v[4];
        float gat[4];
        #pragma unroll
        for (int i = 0; i < 4; i++) {
            v[i]   = flag[i] > 0.0f;
            gat[i] = v[i] ? __ldg(pr + (int)fidx[i]) : 0.0f;  // independent gathers
        }

        const int e0 = tid * 4;
        #pragma unroll
        for (int i = 0; i < 4; i++) {
            if (v[i]) {
                acc += fabsf(gat[i] - vals[i]);
                pv[(e0 + i) / D] = 1;   // benign race: all writers store 1
            }
        }
    }

    // intra-CTA reduce
    #pragma unroll
    for (int off = 16; off > 0; off >>= 1)
        acc += __shfl_xor_sync(0xFFFFFFFFu, acc, off);

    const int wid = tid >> 5;
    const int lid = tid & 31;
    if (lid == 0) wsum[wid] = acc;
    __syncthreads();

    if (tid == 0) {
        float total = 0.0f;
        #pragma unroll
        for (int w = 0; w < NW; w++) total += wsum[w];
        int cnt = 0;
        #pragma unroll
        for (int p = 0; p < PPC; p++) cnt += pv[p];

        // publish partials (plain stores), release, then take a ticket
        ((float*)&g_part[b])[split] = total;
        ((int*)&g_pcnt[b])[split]   = cnt;
        __threadfence();                       // release
        unsigned t = atomicAdd(&g_ticket[b], 1u);
        if (t == SPLITS - 1) {
            __threadfence();                   // acquire before coherent reads
            // one LDG.cg.128 each — bypass (possibly stale) L1
            float4 s4;
            int4   c4;
            asm volatile("ld.global.cg.v4.f32 {%0,%1,%2,%3}, [%4];"
                         : "=f"(s4.x), "=f"(s4.y), "=f"(s4.z), "=f"(s4.w)
                         : "l"(&g_part[b]));
            asm volatile("ld.global.cg.v4.s32 {%0,%1,%2,%3}, [%4];"
                         : "=r"(c4.x), "=r"(c4.y), "=r"(c4.z), "=r"(c4.w)
                         : "l"(&g_pcnt[b]));
            float s = (s4.x + s4.y) + (s4.z + s4.w);   // fixed order: deterministic
            int   c = (c4.x + c4.y) + (c4.z + c4.w);
            out[b] = s / (float)c;
            g_ticket[b] = 0u;                  // only state needing reset
        }
    }
}

extern "C" void kernel_launch(void* const* d_in, const int* in_sizes, int n_in,
                              void* d_out, int out_size)
{
    const float* preds = (const float*)d_in[0];
    const float* gts   = (const float*)d_in[1];
    float* out = (float*)d_out;
    regl1_kernel<<<B * SPLITS, TPC>>>(preds, gts, out);
}

// round 13
// speedup vs baseline: 1.1429x; 1.1429x over previous
#include <cuda_runtime.h>
#include <cstdint>

// RegL1Loss: out[b] = sum_{p,d} valid * |preds[b, idx] - val| / num_people[b]
// B=32, P=64, D=34, L=1048576. gts packed as [...,3] = (val, idx_as_float, flag).
//
// Zero-tail split design:
//   - cudaMemsetAsync zeroes out[] (graph memset node).
//   - 4 CTAs per batch (grid=128). Each CTA scans the ENTIRE batch's gts
//     (coalesced float4, 26KB -> ~204 lines, cheap) so it knows num_people[b]
//     locally/redundantly, but performs the expensive random gathers only for
//     its own quarter (544 L1tex wavefronts/SM instead of 2176).
//   - Each CTA finishes with a single atomicAdd(&out[b], partial/num_people).
//     No tickets, no fences, no finisher CTA, no scratch to reset.

#define B 32
#define P 64
#define D 34
#define PD (P * D)          // 2176
#define L 1048576
#define SPLITS 4
#define GROUPS (PD / 4)     // 544 groups of 4 elements (3 float4s each)
#define GPS (GROUPS / SPLITS) // 136 groups per split
#define TPC 192             // 6 warps
#define NW (TPC / 32)

__global__ __launch_bounds__(TPC) void regl1_kernel(
    const float* __restrict__ preds,
    const float* __restrict__ gts,
    float* __restrict__ out)
{
    const int cta   = blockIdx.x;
    const int b     = cta >> 2;
    const int split = cta & 3;
    const int tid   = threadIdx.x;

    __shared__ int   pv[P];
    __shared__ float wsum[NW];

    if (tid < P) pv[tid] = 0;
    __syncthreads();

    const float4* __restrict__ gbase = (const float4*)(gts + (size_t)b * PD * 3);
    const float* __restrict__ pr = preds + (size_t)b * L;

    const int glo = split * GPS;          // own-split group range
    const int ghi = glo + GPS;

    float acc = 0.0f;
    // Scan ALL 544 groups (full batch) for flags; gather only own split's.
    for (int g = tid; g < GROUPS; g += TPC) {
        const float4* g4 = gbase + (size_t)g * 3;
        float4 a0 = g4[0];
        float4 a1 = g4[1];
        float4 a2 = g4[2];

        float vals[4] = { a0.x, a0.w, a1.z, a2.y };
        float fidx[4] = { a0.y, a1.x, a1.w, a2.z };
        float flag[4] = { a0.z, a1.y, a2.x, a2.w };

        const int e0 = g * 4;
        bool own = (g >= glo) & (g < ghi);

        bool  v[4];
        float gat[4];
        #pragma unroll
        for (int i = 0; i < 4; i++) {
            v[i] = flag[i] > 0.0f;
            if (v[i]) pv[(e0 + i) / D] = 1;   // benign race: all writers store 1
            // independent predicated gathers, only for own quarter
            gat[i] = (own && v[i]) ? __ldg(pr + (int)fidx[i]) : 0.0f;
        }
        if (own) {
            #pragma unroll
            for (int i = 0; i < 4; i++)
                if (v[i]) acc += fabsf(gat[i] - vals[i]);
        }
    }

    // intra-CTA reduce
    #pragma unroll
    for (int off = 16; off > 0; off >>= 1)
        acc += __shfl_xor_sync(0xFFFFFFFFu, acc, off);

    const int wid = tid >> 5;
    const int lid = tid & 31;
    if (lid == 0) wsum[wid] = acc;
    __syncthreads();

    if (wid == 0) {
        float total = (lid < NW) ? wsum[lid] : 0.0f;
        #pragma unroll
        for (int off = 16; off > 0; off >>= 1)
            total += __shfl_xor_sync(0xFFFFFFFFu, total, off);

        int cnt = pv[lid] + pv[lid + 32];
        #pragma unroll
        for (int off = 16; off > 0; off >>= 1)
            cnt += __shfl_xor_sync(0xFFFFFFFFu, cnt, off);

        if (lid == 0)
            atomicAdd(&out[b], total / (float)cnt);   // single tail op per CTA
    }
}

extern "C" void kernel_launch(void* const* d_in, const int* in_sizes, int n_in,
                              void* d_out, int out_size)
{
    const float* preds = (const float*)d_in[0];
    const float* gts   = (const float*)d_in[1];
    float* out = (float*)d_out;
    cudaMemsetAsync(d_out, 0, B * sizeof(float), 0);
    regl1_kernel<<<B * SPLITS, TPC>>>(preds, gts, out);
}